// round 2
// baseline (speedup 1.0000x reference)
#include <cuda_runtime.h>
#include <cstdint>

#define DD   512
#define NB   4
#define LQ   128
#define LM   256
#define TILEL 4

// Scratch (allocation-free rule: __device__ globals)
__device__ float g_q[NB * LQ * DD];    // q = input_emb @ Wq^T + b0   (512 x 512)
__device__ float g_mp[NB * LM * DD];   // mp = memory   @ Wm^T        (1024 x 512)

// ---------------------------------------------------------------------------
// GEMM: C[r,e] = sum_d A[r,d] * W0[e, off+d] (+ b0[e])
// 64x64 tiles, K-step 16, 256 threads, 4x4 micro-tile per thread.
// blocks 0..63  : q  (A=input_emb, M=512,  off=0,   bias)
// blocks 64..191: mp (A=memory,    M=1024, off=512, no bias)
// ---------------------------------------------------------------------------
__global__ __launch_bounds__(256, 2) void gemm_kernel(
    const float* __restrict__ inp, const float* __restrict__ mem,
    const float* __restrict__ W0, const float* __restrict__ b0)
{
    __shared__ float As[16][64];
    __shared__ float Bs[16][64];

    int bx = blockIdx.x;
    const float* A;
    float* C;
    int off, tile_r, tile_e;
    bool bias;
    if (bx < 64) {
        A = inp; C = g_q; off = 0; bias = true;
        tile_r = bx >> 3; tile_e = bx & 7;
    } else {
        int b = bx - 64;
        A = mem; C = g_mp; off = DD; bias = false;
        tile_r = b >> 3; tile_e = b & 7;
    }
    const int r0 = tile_r * 64, e0 = tile_e * 64;
    const int t = threadIdx.x;
    const int tx = t & 15, ty = t >> 4;
    const int lrow = t >> 2;        // 0..63
    const int kq = (t & 3) * 4;     // 0,4,8,12

    float acc[4][4];
#pragma unroll
    for (int i = 0; i < 4; i++)
#pragma unroll
        for (int j = 0; j < 4; j++) acc[i][j] = 0.f;

    const float* aptr = A + (size_t)(r0 + lrow) * DD + kq;
    const float* bptr = W0 + (size_t)(e0 + lrow) * (2 * DD) + off + kq;

    for (int k0 = 0; k0 < DD; k0 += 16) {
        float4 av = *(const float4*)(aptr + k0);
        float4 bv = *(const float4*)(bptr + k0);
        __syncthreads();
        As[kq + 0][lrow] = av.x; As[kq + 1][lrow] = av.y;
        As[kq + 2][lrow] = av.z; As[kq + 3][lrow] = av.w;
        Bs[kq + 0][lrow] = bv.x; Bs[kq + 1][lrow] = bv.y;
        Bs[kq + 2][lrow] = bv.z; Bs[kq + 3][lrow] = bv.w;
        __syncthreads();
#pragma unroll
        for (int k = 0; k < 16; k++) {
            const float4 a4 = *(const float4*)&As[k][ty << 2];
            const float4 b4 = *(const float4*)&Bs[k][tx << 2];
            float ar[4] = {a4.x, a4.y, a4.z, a4.w};
            float br[4] = {b4.x, b4.y, b4.z, b4.w};
#pragma unroll
            for (int i = 0; i < 4; i++)
#pragma unroll
                for (int j = 0; j < 4; j++)
                    acc[i][j] = fmaf(ar[i], br[j], acc[i][j]);
        }
    }

    float4 bb = make_float4(0.f, 0.f, 0.f, 0.f);
    if (bias) bb = *(const float4*)&b0[e0 + (tx << 2)];
#pragma unroll
    for (int i = 0; i < 4; i++) {
        int r = r0 + (ty << 2) + i;
        float4 o;
        o.x = acc[i][0] + bb.x;
        o.y = acc[i][1] + bb.y;
        o.z = acc[i][2] + bb.z;
        o.w = acc[i][3] + bb.w;
        *(float4*)&C[(size_t)r * DD + e0 + (tx << 2)] = o;
    }
}

// ---------------------------------------------------------------------------
// Fused: scores -> masked softmax -> out = attn @ memory
// grid: 128 blocks = 4 n * 32 l-tiles (TILEL=4 rows each), 256 threads.
// Mask is read as 4-byte words (bool promoted to int32/float32 by the
// harness); "true" == any nonzero bit pattern.
// ---------------------------------------------------------------------------
__global__ __launch_bounds__(256) void attn_kernel(
    const float* __restrict__ mem, const unsigned int* __restrict__ mask,
    const float* __restrict__ w1, const float* __restrict__ b1,
    float* __restrict__ out)
{
    __shared__ float sc[TILEL][LM];

    const int b = blockIdx.x;
    const int n = b >> 5;
    const int l0 = (b & 31) * TILEL;
    const int t = threadIdx.x;
    const int w = t >> 5, lane = t & 31;

    // --- load q (4 rows x 16 d per lane) and w1 into registers ---
    float qr[4][16];
    float wr[16];
    {
        const float* qrow0 = g_q + (size_t)(n * LQ + l0) * DD;
#pragma unroll
        for (int l = 0; l < 4; l++) {
#pragma unroll
            for (int c = 0; c < 4; c++) {
                float4 v = *(const float4*)&qrow0[l * DD + c * 128 + lane * 4];
                qr[l][c * 4 + 0] = v.x; qr[l][c * 4 + 1] = v.y;
                qr[l][c * 4 + 2] = v.z; qr[l][c * 4 + 3] = v.w;
            }
        }
#pragma unroll
        for (int c = 0; c < 4; c++) {
            float4 v = *(const float4*)&w1[c * 128 + lane * 4];
            wr[c * 4 + 0] = v.x; wr[c * 4 + 1] = v.y;
            wr[c * 4 + 2] = v.z; wr[c * 4 + 3] = v.w;
        }
    }
    const float b1v = b1[0];

    // --- Phase 1: scores ---
    const float* mpn = g_mp + (size_t)n * LM * DD;
    const int m0 = w * 32;
    for (int mi = 0; mi < 32; mi++) {
        const int m = m0 + mi;
        const float* mrow = mpn + (size_t)m * DD;
        float mr[16];
#pragma unroll
        for (int c = 0; c < 4; c++) {
            float4 v = *(const float4*)&mrow[c * 128 + lane * 4];
            mr[c * 4 + 0] = v.x; mr[c * 4 + 1] = v.y;
            mr[c * 4 + 2] = v.z; mr[c * 4 + 3] = v.w;
        }
        float a[4] = {0.f, 0.f, 0.f, 0.f};
#pragma unroll
        for (int d = 0; d < 16; d++) {
            const float me = mr[d];
            const float wd = wr[d];
#pragma unroll
            for (int l = 0; l < 4; l++) {
                float x = qr[l][d] + me;
                float th;
                asm("tanh.approx.f32 %0, %1;" : "=f"(th) : "f"(x));
                a[l] = fmaf(wd, th, a[l]);
            }
        }
#pragma unroll
        for (int l = 0; l < 4; l++) {
#pragma unroll
            for (int o = 16; o > 0; o >>= 1)
                a[l] += __shfl_xor_sync(0xffffffffu, a[l], o);
        }
        if (lane < 4) {
            float v = (lane & 2) ? ((lane & 1) ? a[3] : a[2])
                                 : ((lane & 1) ? a[1] : a[0]);
            sc[lane][m] = v + b1v;
        }
    }
    __syncthreads();

    // --- Phase 2: masked softmax (warps 0..3, one l row each) ---
    if (w < 4) {
        const int l = w;
        const unsigned int* mrow = mask + (size_t)(n * LQ + l0 + l) * LM;
        const float NEG = -3.402823466e38f;
        float s[8];
        float mx = NEG;
#pragma unroll
        for (int k = 0; k < 8; k++) {
            int m = lane + 32 * k;
            float v = sc[l][m];
            if (mrow[m] == 0u) v = NEG;   // nonzero bits == true (int32 or f32)
            s[k] = v;
            mx = fmaxf(mx, v);
        }
#pragma unroll
        for (int o = 16; o > 0; o >>= 1)
            mx = fmaxf(mx, __shfl_xor_sync(0xffffffffu, mx, o));
        float sum = 0.f;
#pragma unroll
        for (int k = 0; k < 8; k++) {
            s[k] = __expf(s[k] - mx);
            sum += s[k];
        }
#pragma unroll
        for (int o = 16; o > 0; o >>= 1)
            sum += __shfl_xor_sync(0xffffffffu, sum, o);
        const float inv = 1.f / sum;
#pragma unroll
        for (int k = 0; k < 8; k++)
            sc[l][lane + 32 * k] = s[k] * inv;
    }
    __syncthreads();

    // --- Phase 3: out = attn @ memory ---
    {
        const int l = t >> 6;
        const int dbase = (t & 63) * 8;
        const float* memn = mem + (size_t)n * LM * DD;
        float4 o0 = make_float4(0.f, 0.f, 0.f, 0.f);
        float4 o1 = make_float4(0.f, 0.f, 0.f, 0.f);
#pragma unroll 4
        for (int m = 0; m < LM; m++) {
            const float a = sc[l][m];
            const float4 v0 = *(const float4*)&memn[(size_t)m * DD + dbase];
            const float4 v1 = *(const float4*)&memn[(size_t)m * DD + dbase + 4];
            o0.x = fmaf(a, v0.x, o0.x); o0.y = fmaf(a, v0.y, o0.y);
            o0.z = fmaf(a, v0.z, o0.z); o0.w = fmaf(a, v0.w, o0.w);
            o1.x = fmaf(a, v1.x, o1.x); o1.y = fmaf(a, v1.y, o1.y);
            o1.z = fmaf(a, v1.z, o1.z); o1.w = fmaf(a, v1.w, o1.w);
        }
        float* orow = out + (size_t)(n * LQ + l0 + l) * DD + dbase;
        *(float4*)&orow[0] = o0;
        *(float4*)&orow[4] = o1;
    }
}

extern "C" void kernel_launch(void* const* d_in, const int* in_sizes, int n_in,
                              void* d_out, int out_size)
{
    const float*        inp  = (const float*)d_in[0];        // (4,128,512)
    const float*        mem  = (const float*)d_in[1];        // (4,256,512)
    const unsigned int* mask = (const unsigned int*)d_in[2]; // (4,128,256) bool->4B
    const float*        W0   = (const float*)d_in[3];        // (512,1024)
    const float*        b0   = (const float*)d_in[4];        // (512)
    const float*        w1   = (const float*)d_in[5];        // (1,512)
    const float*        b1   = (const float*)d_in[6];        // (1)
    float* out = (float*)d_out;                              // (4,128,512)

    gemm_kernel<<<192, 256>>>(inp, mem, W0, b0);
    attn_kernel<<<128, 256>>>(mem, mask, w1, b1, out);
}

// round 3
// speedup vs baseline: 1.1273x; 1.1273x over previous
#include <cuda_runtime.h>
#include <cstdint>

#define DD   512
#define NB   4
#define LQ   128
#define LM   256

// Scratch (allocation-free rule: __device__ globals)
__device__ float g_q[NB * LQ * DD];    // q = input_emb @ Wq^T + b0
__device__ float g_mp[NB * LM * DD];   // mp = memory   @ Wm^T
__device__ float g_sc[NB * LQ * LM];   // raw scores (pre-mask/softmax)

// ---------------------------------------------------------------------------
// GEMM: C[r,e] = sum_d A[r,d] * W0[e, off+d] (+ b0[e])
// 64x64 tiles, K-step 16, 256 threads, 4x4 micro-tile per thread.
// ---------------------------------------------------------------------------
__global__ __launch_bounds__(256, 2) void gemm_kernel(
    const float* __restrict__ inp, const float* __restrict__ mem,
    const float* __restrict__ W0, const float* __restrict__ b0)
{
    __shared__ float As[16][64];
    __shared__ float Bs[16][64];

    int bx = blockIdx.x;
    const float* A;
    float* C;
    int off, tile_r, tile_e;
    bool bias;
    if (bx < 64) {
        A = inp; C = g_q; off = 0; bias = true;
        tile_r = bx >> 3; tile_e = bx & 7;
    } else {
        int b = bx - 64;
        A = mem; C = g_mp; off = DD; bias = false;
        tile_r = b >> 3; tile_e = b & 7;
    }
    const int r0 = tile_r * 64, e0 = tile_e * 64;
    const int t = threadIdx.x;
    const int tx = t & 15, ty = t >> 4;
    const int lrow = t >> 2;
    const int kq = (t & 3) * 4;

    float acc[4][4];
#pragma unroll
    for (int i = 0; i < 4; i++)
#pragma unroll
        for (int j = 0; j < 4; j++) acc[i][j] = 0.f;

    const float* aptr = A + (size_t)(r0 + lrow) * DD + kq;
    const float* bptr = W0 + (size_t)(e0 + lrow) * (2 * DD) + off + kq;

    for (int k0 = 0; k0 < DD; k0 += 16) {
        float4 av = *(const float4*)(aptr + k0);
        float4 bv = *(const float4*)(bptr + k0);
        __syncthreads();
        As[kq + 0][lrow] = av.x; As[kq + 1][lrow] = av.y;
        As[kq + 2][lrow] = av.z; As[kq + 3][lrow] = av.w;
        Bs[kq + 0][lrow] = bv.x; Bs[kq + 1][lrow] = bv.y;
        Bs[kq + 2][lrow] = bv.z; Bs[kq + 3][lrow] = bv.w;
        __syncthreads();
#pragma unroll
        for (int k = 0; k < 16; k++) {
            const float4 a4 = *(const float4*)&As[k][ty << 2];
            const float4 b4 = *(const float4*)&Bs[k][tx << 2];
            float ar[4] = {a4.x, a4.y, a4.z, a4.w};
            float br[4] = {b4.x, b4.y, b4.z, b4.w};
#pragma unroll
            for (int i = 0; i < 4; i++)
#pragma unroll
                for (int j = 0; j < 4; j++)
                    acc[i][j] = fmaf(ar[i], br[j], acc[i][j]);
        }
    }

    float4 bb = make_float4(0.f, 0.f, 0.f, 0.f);
    if (bias) bb = *(const float4*)&b0[e0 + (tx << 2)];
#pragma unroll
    for (int i = 0; i < 4; i++) {
        int r = r0 + (ty << 2) + i;
        float4 o;
        o.x = acc[i][0] + bb.x;
        o.y = acc[i][1] + bb.y;
        o.z = acc[i][2] + bb.z;
        o.w = acc[i][3] + bb.w;
        *(float4*)&C[(size_t)r * DD + e0 + (tx << 2)] = o;
    }
}

// ---------------------------------------------------------------------------
// Score kernel: g_sc[n,l,m] = b1 + sum_d w1[d]*tanh(q[n,l,d]+mp[n,m,d])
// grid = 1024 blocks: n(4) x l-tile(32, 4 rows) x m-split(8, 32 m's).
// 256 threads; warp w handles 4 m's: m = m0 + w*4 + {0..3}.
// Each lane holds 16 d's of q (4 rows) and w1; mp row streamed 4x LDG.128.
// ---------------------------------------------------------------------------
__global__ __launch_bounds__(256, 2) void score_kernel(
    const float* __restrict__ w1, const float* __restrict__ b1)
{
    const int b = blockIdx.x;
    const int n = b >> 8;
    const int rem = b & 255;
    const int l0 = (rem >> 3) * 4;
    const int m0 = (rem & 7) * 32;
    const int t = threadIdx.x;
    const int w = t >> 5, lane = t & 31;

    float qr[4][16];
    float wr[16];
    {
        const float* qrow0 = g_q + (size_t)(n * LQ + l0) * DD;
#pragma unroll
        for (int l = 0; l < 4; l++) {
#pragma unroll
            for (int c = 0; c < 4; c++) {
                float4 v = *(const float4*)&qrow0[l * DD + c * 128 + lane * 4];
                qr[l][c * 4 + 0] = v.x; qr[l][c * 4 + 1] = v.y;
                qr[l][c * 4 + 2] = v.z; qr[l][c * 4 + 3] = v.w;
            }
        }
#pragma unroll
        for (int c = 0; c < 4; c++) {
            float4 v = *(const float4*)&w1[c * 128 + lane * 4];
            wr[c * 4 + 0] = v.x; wr[c * 4 + 1] = v.y;
            wr[c * 4 + 2] = v.z; wr[c * 4 + 3] = v.w;
        }
    }
    const float b1v = b1[0];

    const float* mpn = g_mp + (size_t)n * LM * DD;
#pragma unroll
    for (int mi = 0; mi < 4; mi++) {
        const int m = m0 + w * 4 + mi;
        const float* mrow = mpn + (size_t)m * DD;
        float mr[16];
#pragma unroll
        for (int c = 0; c < 4; c++) {
            float4 v = *(const float4*)&mrow[c * 128 + lane * 4];
            mr[c * 4 + 0] = v.x; mr[c * 4 + 1] = v.y;
            mr[c * 4 + 2] = v.z; mr[c * 4 + 3] = v.w;
        }
        float a[4] = {0.f, 0.f, 0.f, 0.f};
#pragma unroll
        for (int d = 0; d < 16; d++) {
            const float me = mr[d];
            const float wd = wr[d];
#pragma unroll
            for (int l = 0; l < 4; l++) {
                float x = qr[l][d] + me;
                float th;
                asm("tanh.approx.f32 %0, %1;" : "=f"(th) : "f"(x));
                a[l] = fmaf(wd, th, a[l]);
            }
        }
#pragma unroll
        for (int l = 0; l < 4; l++) {
#pragma unroll
            for (int o = 16; o > 0; o >>= 1)
                a[l] += __shfl_xor_sync(0xffffffffu, a[l], o);
        }
        if (lane < 4) {
            float v = (lane & 2) ? ((lane & 1) ? a[3] : a[2])
                                 : ((lane & 1) ? a[1] : a[0]);
            g_sc[(size_t)(n * LQ + l0 + lane) * LM + m] = v + b1v;
        }
    }
}

// ---------------------------------------------------------------------------
// Softmax + output: out[n,l,:] = softmax(mask(sc[n,l,:])) @ memory[n]
// grid = 512 blocks: n(4) x l-tile(32, 4 rows) x d-split(4, 128 d's).
// 128 threads. Warp w softmaxes row l=w into smem; then warp l streams its
// 128-d slice of memory[n] (identical slice across warps -> L1 reuse).
// ---------------------------------------------------------------------------
__global__ __launch_bounds__(128) void out_kernel(
    const float* __restrict__ mem, const unsigned int* __restrict__ mask,
    float* __restrict__ out)
{
    __shared__ float att[4][LM];

    const int b = blockIdx.x;
    const int n = b >> 7;
    const int rem = b & 127;
    const int l0 = (rem >> 2) * 4;
    const int d0 = (rem & 3) * 128;
    const int t = threadIdx.x;
    const int w = t >> 5, lane = t & 31;

    // --- masked softmax, warp w -> row l0+w ---
    {
        const int l = w;
        const float* srow = g_sc + (size_t)(n * LQ + l0 + l) * LM;
        const unsigned int* mrow = mask + (size_t)(n * LQ + l0 + l) * LM;
        const float NEG = -3.402823466e38f;
        float s[8];
        float mx = NEG;
#pragma unroll
        for (int k = 0; k < 8; k++) {
            int m = lane + 32 * k;
            float v = srow[m];
            if (mrow[m] == 0u) v = NEG;   // bool promoted: nonzero bits == true
            s[k] = v;
            mx = fmaxf(mx, v);
        }
#pragma unroll
        for (int o = 16; o > 0; o >>= 1)
            mx = fmaxf(mx, __shfl_xor_sync(0xffffffffu, mx, o));
        float sum = 0.f;
#pragma unroll
        for (int k = 0; k < 8; k++) {
            s[k] = __expf(s[k] - mx);
            sum += s[k];
        }
#pragma unroll
        for (int o = 16; o > 0; o >>= 1)
            sum += __shfl_xor_sync(0xffffffffu, sum, o);
        const float inv = 1.f / sum;
#pragma unroll
        for (int k = 0; k < 8; k++)
            att[l][lane + 32 * k] = s[k] * inv;
    }
    __syncthreads();

    // --- out[l, d0 + lane*4 .. +3] = sum_m att[l][m] * memory[n,m,d] ---
    {
        const int l = w;
        const int dbase = d0 + lane * 4;
        const float* memn = mem + (size_t)n * LM * DD + dbase;
        float4 o0 = make_float4(0.f, 0.f, 0.f, 0.f);
#pragma unroll 8
        for (int m = 0; m < LM; m++) {
            const float a = att[l][m];
            const float4 v = *(const float4*)&memn[(size_t)m * DD];
            o0.x = fmaf(a, v.x, o0.x); o0.y = fmaf(a, v.y, o0.y);
            o0.z = fmaf(a, v.z, o0.z); o0.w = fmaf(a, v.w, o0.w);
        }
        *(float4*)&out[(size_t)(n * LQ + l0 + l) * DD + dbase] = o0;
    }
}

extern "C" void kernel_launch(void* const* d_in, const int* in_sizes, int n_in,
                              void* d_out, int out_size)
{
    const float*        inp  = (const float*)d_in[0];        // (4,128,512)
    const float*        mem  = (const float*)d_in[1];        // (4,256,512)
    const unsigned int* mask = (const unsigned int*)d_in[2]; // (4,128,256) bool->4B
    const float*        W0   = (const float*)d_in[3];        // (512,1024)
    const float*        b0   = (const float*)d_in[4];        // (512)
    const float*        w1   = (const float*)d_in[5];        // (1,512)
    const float*        b1   = (const float*)d_in[6];        // (1)
    float* out = (float*)d_out;                              // (4,128,512)

    gemm_kernel<<<192, 256>>>(inp, mem, W0, b0);
    score_kernel<<<1024, 256>>>(w1, b1);
    out_kernel<<<512, 128>>>(mem, mask, out);
}

// round 4
// speedup vs baseline: 1.3324x; 1.1819x over previous
#include <cuda_runtime.h>
#include <cstdint>

#define DD   512
#define NB   4
#define LQ   128
#define LM   256

// Scratch (allocation-free rule: __device__ globals)
__device__ float g_q[NB * LQ * DD];    // q = input_emb @ Wq^T + b0
__device__ float g_mp[NB * LM * DD];   // mp = memory   @ Wm^T
__device__ float g_sc[NB * LQ * LM];   // raw scores (pre-mask/softmax)

#define TF32(u, f) asm("cvt.rna.tf32.f32 %0, %1;" : "=r"(u) : "f"(f))

__device__ __forceinline__ void mma_tf32(
    float& c0, float& c1, float& c2, float& c3,
    uint32_t a0, uint32_t a1, uint32_t a2, uint32_t a3,
    uint32_t b0, uint32_t b1)
{
    asm volatile(
        "mma.sync.aligned.m16n8k8.row.col.f32.tf32.tf32.f32 "
        "{%0,%1,%2,%3}, {%4,%5,%6,%7}, {%8,%9}, {%0,%1,%2,%3};"
        : "+f"(c0), "+f"(c1), "+f"(c2), "+f"(c3)
        : "r"(a0), "r"(a1), "r"(a2), "r"(a3), "r"(b0), "r"(b1));
}

// ---------------------------------------------------------------------------
// Tensor-core GEMM (tf32): C[r,e] = sum_d A[r,d] * W0[e, off+d] (+ b0[e])
// Tile 32(M) x 64(N), 128 threads (4 warps; warp w covers n-slice w*16..+16,
// full 32 M via two m16 tiles). K-step 32 (4x k8).
// blocks 0..127  : q  (A=input_emb, 512 rows,  off=0,   bias)
// blocks 128..383: mp (A=memory,   1024 rows,  off=512, no bias)
// ---------------------------------------------------------------------------
__global__ __launch_bounds__(128, 8) void gemm_tc_kernel(
    const float* __restrict__ inp, const float* __restrict__ mem,
    const float* __restrict__ W0, const float* __restrict__ b0)
{
    __shared__ uint32_t As[32][33];
    __shared__ uint32_t Bs[64][33];

    const int bx = blockIdx.x;
    const float* A;
    float* C;
    int off, r0, e0;
    bool bias;
    if (bx < 128) {
        A = inp; C = g_q; off = 0; bias = true;
        r0 = (bx >> 3) * 32; e0 = (bx & 7) * 64;
    } else {
        const int i = bx - 128;
        A = mem; C = g_mp; off = DD; bias = false;
        r0 = (i >> 3) * 32; e0 = (i & 7) * 64;
    }

    const int t = threadIdx.x;
    const int wid = t >> 5, lane = t & 31;
    const int lx = lane & 3, ly = lane >> 2;   // frag coords
    const int lr = t >> 3;                     // 0..15
    const int lc = (t & 7) * 4;                // 0,4,...,28

    float c[2][2][4];
#pragma unroll
    for (int mt = 0; mt < 2; mt++)
#pragma unroll
        for (int nt = 0; nt < 2; nt++)
#pragma unroll
            for (int i = 0; i < 4; i++) c[mt][nt][i] = 0.f;

    const float* aptr = A + (size_t)r0 * DD;
    const float* bptr = W0 + (size_t)e0 * (2 * DD) + off;

    for (int k0 = 0; k0 < DD; k0 += 32) {
        // load + convert A (32x32) and B (64x32)
        float4 av0 = *(const float4*)&aptr[(size_t)(lr     ) * DD + k0 + lc];
        float4 av1 = *(const float4*)&aptr[(size_t)(lr + 16) * DD + k0 + lc];
        float4 bv0 = *(const float4*)&bptr[(size_t)(lr     ) * (2 * DD) + k0 + lc];
        float4 bv1 = *(const float4*)&bptr[(size_t)(lr + 16) * (2 * DD) + k0 + lc];
        float4 bv2 = *(const float4*)&bptr[(size_t)(lr + 32) * (2 * DD) + k0 + lc];
        float4 bv3 = *(const float4*)&bptr[(size_t)(lr + 48) * (2 * DD) + k0 + lc];
        __syncthreads();
        uint32_t u;
        TF32(u, av0.x); As[lr][lc]          = u;
        TF32(u, av0.y); As[lr][lc + 1]      = u;
        TF32(u, av0.z); As[lr][lc + 2]      = u;
        TF32(u, av0.w); As[lr][lc + 3]      = u;
        TF32(u, av1.x); As[lr + 16][lc]     = u;
        TF32(u, av1.y); As[lr + 16][lc + 1] = u;
        TF32(u, av1.z); As[lr + 16][lc + 2] = u;
        TF32(u, av1.w); As[lr + 16][lc + 3] = u;
        TF32(u, bv0.x); Bs[lr][lc]          = u;
        TF32(u, bv0.y); Bs[lr][lc + 1]      = u;
        TF32(u, bv0.z); Bs[lr][lc + 2]      = u;
        TF32(u, bv0.w); Bs[lr][lc + 3]      = u;
        TF32(u, bv1.x); Bs[lr + 16][lc]     = u;
        TF32(u, bv1.y); Bs[lr + 16][lc + 1] = u;
        TF32(u, bv1.z); Bs[lr + 16][lc + 2] = u;
        TF32(u, bv1.w); Bs[lr + 16][lc + 3] = u;
        TF32(u, bv2.x); Bs[lr + 32][lc]     = u;
        TF32(u, bv2.y); Bs[lr + 32][lc + 1] = u;
        TF32(u, bv2.z); Bs[lr + 32][lc + 2] = u;
        TF32(u, bv2.w); Bs[lr + 32][lc + 3] = u;
        TF32(u, bv3.x); Bs[lr + 48][lc]     = u;
        TF32(u, bv3.y); Bs[lr + 48][lc + 1] = u;
        TF32(u, bv3.z); Bs[lr + 48][lc + 2] = u;
        TF32(u, bv3.w); Bs[lr + 48][lc + 3] = u;
        __syncthreads();

#pragma unroll
        for (int k8 = 0; k8 < 4; k8++) {
            const int kb = k8 * 8;
            uint32_t a[2][4], b[2][2];
#pragma unroll
            for (int mt = 0; mt < 2; mt++) {
                a[mt][0] = As[mt * 16 + ly][kb + lx];
                a[mt][1] = As[mt * 16 + ly + 8][kb + lx];
                a[mt][2] = As[mt * 16 + ly][kb + lx + 4];
                a[mt][3] = As[mt * 16 + ly + 8][kb + lx + 4];
            }
#pragma unroll
            for (int nt = 0; nt < 2; nt++) {
                const int nb = wid * 16 + nt * 8 + ly;
                b[nt][0] = Bs[nb][kb + lx];
                b[nt][1] = Bs[nb][kb + lx + 4];
            }
#pragma unroll
            for (int mt = 0; mt < 2; mt++)
#pragma unroll
                for (int nt = 0; nt < 2; nt++)
                    mma_tf32(c[mt][nt][0], c[mt][nt][1], c[mt][nt][2], c[mt][nt][3],
                             a[mt][0], a[mt][1], a[mt][2], a[mt][3],
                             b[nt][0], b[nt][1]);
        }
    }

    // epilogue: bias + store (float2 per c-pair)
#pragma unroll
    for (int mt = 0; mt < 2; mt++) {
#pragma unroll
        for (int nt = 0; nt < 2; nt++) {
            const int col = e0 + wid * 16 + nt * 8 + 2 * lx;
            float bx0 = 0.f, bx1 = 0.f;
            if (bias) { bx0 = b0[col]; bx1 = b0[col + 1]; }
            const int rA = r0 + mt * 16 + ly;
            float2 v0 = make_float2(c[mt][nt][0] + bx0, c[mt][nt][1] + bx1);
            float2 v1 = make_float2(c[mt][nt][2] + bx0, c[mt][nt][3] + bx1);
            *(float2*)&C[(size_t)rA * DD + col]       = v0;
            *(float2*)&C[(size_t)(rA + 8) * DD + col] = v1;
        }
    }
}

// ---------------------------------------------------------------------------
// Score kernel: g_sc[n,l,m] = b1 + sum_d w1[d]*tanh(q[n,l,d]+mp[n,m,d])
// grid = 1024 blocks: n(4) x l-tile(32, 4 rows) x m-split(8, 32 m's).
// ---------------------------------------------------------------------------
__global__ __launch_bounds__(256, 2) void score_kernel(
    const float* __restrict__ w1, const float* __restrict__ b1)
{
    const int b = blockIdx.x;
    const int n = b >> 8;
    const int rem = b & 255;
    const int l0 = (rem >> 3) * 4;
    const int m0 = (rem & 7) * 32;
    const int t = threadIdx.x;
    const int w = t >> 5, lane = t & 31;

    float qr[4][16];
    float wr[16];
    {
        const float* qrow0 = g_q + (size_t)(n * LQ + l0) * DD;
#pragma unroll
        for (int l = 0; l < 4; l++) {
#pragma unroll
            for (int c = 0; c < 4; c++) {
                float4 v = *(const float4*)&qrow0[l * DD + c * 128 + lane * 4];
                qr[l][c * 4 + 0] = v.x; qr[l][c * 4 + 1] = v.y;
                qr[l][c * 4 + 2] = v.z; qr[l][c * 4 + 3] = v.w;
            }
        }
#pragma unroll
        for (int c = 0; c < 4; c++) {
            float4 v = *(const float4*)&w1[c * 128 + lane * 4];
            wr[c * 4 + 0] = v.x; wr[c * 4 + 1] = v.y;
            wr[c * 4 + 2] = v.z; wr[c * 4 + 3] = v.w;
        }
    }
    const float b1v = b1[0];

    const float* mpn = g_mp + (size_t)n * LM * DD;
#pragma unroll
    for (int mi = 0; mi < 4; mi++) {
        const int m = m0 + w * 4 + mi;
        const float* mrow = mpn + (size_t)m * DD;
        float mr[16];
#pragma unroll
        for (int c = 0; c < 4; c++) {
            float4 v = *(const float4*)&mrow[c * 128 + lane * 4];
            mr[c * 4 + 0] = v.x; mr[c * 4 + 1] = v.y;
            mr[c * 4 + 2] = v.z; mr[c * 4 + 3] = v.w;
        }
        float a[4] = {0.f, 0.f, 0.f, 0.f};
#pragma unroll
        for (int d = 0; d < 16; d++) {
            const float me = mr[d];
            const float wd = wr[d];
#pragma unroll
            for (int l = 0; l < 4; l++) {
                float x = qr[l][d] + me;
                float th;
                asm("tanh.approx.f32 %0, %1;" : "=f"(th) : "f"(x));
                a[l] = fmaf(wd, th, a[l]);
            }
        }
#pragma unroll
        for (int l = 0; l < 4; l++) {
#pragma unroll
            for (int o = 16; o > 0; o >>= 1)
                a[l] += __shfl_xor_sync(0xffffffffu, a[l], o);
        }
        if (lane < 4) {
            float v = (lane & 2) ? ((lane & 1) ? a[3] : a[2])
                                 : ((lane & 1) ? a[1] : a[0]);
            g_sc[(size_t)(n * LQ + l0 + lane) * LM + m] = v + b1v;
        }
    }
}

// ---------------------------------------------------------------------------
// Softmax + output: out[n,l,:] = softmax(mask(sc[n,l,:])) @ memory[n]
// grid = 512 blocks: n(4) x l-tile(32, 4 rows) x d-split(4, 128 d's).
// ---------------------------------------------------------------------------
__global__ __launch_bounds__(128) void out_kernel(
    const float* __restrict__ mem, const unsigned int* __restrict__ mask,
    float* __restrict__ out)
{
    __shared__ float att[4][LM];

    const int b = blockIdx.x;
    const int n = b >> 7;
    const int rem = b & 127;
    const int l0 = (rem >> 2) * 4;
    const int d0 = (rem & 3) * 128;
    const int t = threadIdx.x;
    const int w = t >> 5, lane = t & 31;

    {
        const int l = w;
        const float* srow = g_sc + (size_t)(n * LQ + l0 + l) * LM;
        const unsigned int* mrow = mask + (size_t)(n * LQ + l0 + l) * LM;
        const float NEG = -3.402823466e38f;
        float s[8];
        float mx = NEG;
#pragma unroll
        for (int k = 0; k < 8; k++) {
            int m = lane + 32 * k;
            float v = srow[m];
            if (mrow[m] == 0u) v = NEG;   // bool promoted: nonzero bits == true
            s[k] = v;
            mx = fmaxf(mx, v);
        }
#pragma unroll
        for (int o = 16; o > 0; o >>= 1)
            mx = fmaxf(mx, __shfl_xor_sync(0xffffffffu, mx, o));
        float sum = 0.f;
#pragma unroll
        for (int k = 0; k < 8; k++) {
            s[k] = __expf(s[k] - mx);
            sum += s[k];
        }
#pragma unroll
        for (int o = 16; o > 0; o >>= 1)
            sum += __shfl_xor_sync(0xffffffffu, sum, o);
        const float inv = 1.f / sum;
#pragma unroll
        for (int k = 0; k < 8; k++)
            att[l][lane + 32 * k] = s[k] * inv;
    }
    __syncthreads();

    {
        const int l = w;
        const int dbase = d0 + lane * 4;
        const float* memn = mem + (size_t)n * LM * DD + dbase;
        float4 o0 = make_float4(0.f, 0.f, 0.f, 0.f);
#pragma unroll 8
        for (int m = 0; m < LM; m++) {
            const float a = att[l][m];
            const float4 v = *(const float4*)&memn[(size_t)m * DD];
            o0.x = fmaf(a, v.x, o0.x); o0.y = fmaf(a, v.y, o0.y);
            o0.z = fmaf(a, v.z, o0.z); o0.w = fmaf(a, v.w, o0.w);
        }
        *(float4*)&out[(size_t)(n * LQ + l0 + l) * DD + dbase] = o0;
    }
}

extern "C" void kernel_launch(void* const* d_in, const int* in_sizes, int n_in,
                              void* d_out, int out_size)
{
    const float*        inp  = (const float*)d_in[0];        // (4,128,512)
    const float*        mem  = (const float*)d_in[1];        // (4,256,512)
    const unsigned int* mask = (const unsigned int*)d_in[2]; // (4,128,256) bool->4B
    const float*        W0   = (const float*)d_in[3];        // (512,1024)
    const float*        b0   = (const float*)d_in[4];        // (512)
    const float*        w1   = (const float*)d_in[5];        // (1,512)
    const float*        b1   = (const float*)d_in[6];        // (1)
    float* out = (float*)d_out;                              // (4,128,512)

    gemm_tc_kernel<<<384, 128>>>(inp, mem, W0, b0);
    score_kernel<<<1024, 256>>>(w1, b1);
    out_kernel<<<512, 128>>>(mem, mask, out);
}

// round 5
// speedup vs baseline: 1.8441x; 1.3840x over previous
#include <cuda_runtime.h>
#include <cstdint>

#define DD   512
#define NB   4
#define LQ   128
#define LM   256

// Scratch (allocation-free rule: __device__ globals)
__device__ float g_q[NB * LQ * DD];    // q = input_emb @ Wq^T + b0
__device__ float g_mp[NB * LM * DD];   // mp = memory   @ Wm^T
__device__ float g_sc[NB * LQ * LM];   // raw scores (pre-mask/softmax)

__device__ __forceinline__ void mma_tf32(
    float& c0, float& c1, float& c2, float& c3,
    uint32_t a0, uint32_t a1, uint32_t a2, uint32_t a3,
    uint32_t b0, uint32_t b1)
{
    asm volatile(
        "mma.sync.aligned.m16n8k8.row.col.f32.tf32.tf32.f32 "
        "{%0,%1,%2,%3}, {%4,%5,%6,%7}, {%8,%9}, {%0,%1,%2,%3};"
        : "+f"(c0), "+f"(c1), "+f"(c2), "+f"(c3)
        : "r"(a0), "r"(a1), "r"(a2), "r"(a3), "r"(b0), "r"(b1));
}

__device__ __forceinline__ void cpa16(uint32_t dst, const float* src)
{
    asm volatile("cp.async.cg.shared.global [%0], [%1], 16;\n"
                 :: "r"(dst), "l"(src));
}

// ---------------------------------------------------------------------------
// Tensor-core GEMM (tf32, cp.async double-buffered, XOR-swizzled smem):
//   C[r,e] = sum_d A[r,d] * W0[e, off+d] (+ b0[e])
// Tile 32(M) x 64(N), 128 threads (4 warps; warp w -> n-slice w*16..+16,
// 2 m16 x 2 n8 frags). K-step 32, 16 iterations, 2 smem stages.
// fp32 bits fed raw to tf32 MMA (HW mantissa truncation).
// Swizzle: physical col = col ^ (4*(row&7))  (rows of 32 floats).
// blocks 0..127  : q  (A=input_emb, 512 rows,  off=0,   bias)
// blocks 128..383: mp (A=memory,   1024 rows,  off=512, no bias)
// ---------------------------------------------------------------------------
__global__ __launch_bounds__(128, 6) void gemm_tc_kernel(
    const float* __restrict__ inp, const float* __restrict__ mem,
    const float* __restrict__ W0, const float* __restrict__ b0)
{
    __shared__ float As[2][32 * 32];
    __shared__ float Bs[2][64 * 32];

    const int bx = blockIdx.x;
    const float* A;
    float* C;
    int off, r0, e0;
    bool bias;
    if (bx < 128) {
        A = inp; C = g_q; off = 0; bias = true;
        r0 = (bx >> 3) * 32; e0 = (bx & 7) * 64;
    } else {
        const int i = bx - 128;
        A = mem; C = g_mp; off = DD; bias = false;
        r0 = (i >> 3) * 32; e0 = (i & 7) * 64;
    }

    const int t = threadIdx.x;
    const int wid = t >> 5, lane = t & 31;
    const int lx = lane & 3, ly = lane >> 2;
    const int swz = 4 * ly;

    const uint32_t sAs = (uint32_t)__cvta_generic_to_shared(As);
    const uint32_t sBs = (uint32_t)__cvta_generic_to_shared(Bs);

    float c[2][2][4];
#pragma unroll
    for (int mt = 0; mt < 2; mt++)
#pragma unroll
        for (int nt = 0; nt < 2; nt++)
#pragma unroll
            for (int i = 0; i < 4; i++) c[mt][nt][i] = 0.f;

    const float* aptr = A + (size_t)r0 * DD;
    const float* bptr = W0 + (size_t)e0 * (2 * DD) + off;

    // stage loader: A 32x32 (2 chunks/thread), B 64x32 (4 chunks/thread)
    auto load_stage = [&](int s, int k0) {
#pragma unroll
        for (int i = 0; i < 2; i++) {
            const int cid = 2 * t + i;
            const int row = cid >> 3, cc = (cid & 7) * 4;
            const int pc = cc ^ ((row & 7) * 4);
            cpa16(sAs + (uint32_t)((s * 1024 + row * 32 + pc) * 4),
                  aptr + (size_t)row * DD + k0 + cc);
        }
#pragma unroll
        for (int i = 0; i < 4; i++) {
            const int cid = t + i * 128;
            const int row = cid >> 3, cc = (cid & 7) * 4;
            const int pc = cc ^ ((row & 7) * 4);
            cpa16(sBs + (uint32_t)((s * 2048 + row * 32 + pc) * 4),
                  bptr + (size_t)row * (2 * DD) + k0 + cc);
        }
        asm volatile("cp.async.commit_group;\n" ::: "memory");
    };

    load_stage(0, 0);

    const uint32_t* AsU = (const uint32_t*)As;
    const uint32_t* BsU = (const uint32_t*)Bs;

    for (int it = 0; it < 16; it++) {
        if (it + 1 < 16) load_stage((it + 1) & 1, (it + 1) * 32);
        else asm volatile("cp.async.commit_group;\n" ::: "memory");
        asm volatile("cp.async.wait_group 1;\n" ::: "memory");
        __syncthreads();

        const int s = it & 1;
        const uint32_t* Ab = AsU + s * 1024;
        const uint32_t* Bb = BsU + s * 2048;
#pragma unroll
        for (int k8 = 0; k8 < 4; k8++) {
            const int c0 = (k8 * 8 + lx) ^ swz;
            const int c1 = c0 ^ 4;
            uint32_t a[2][4], b[2][2];
#pragma unroll
            for (int mt = 0; mt < 2; mt++) {
                const int rA = mt * 16 + ly;
                a[mt][0] = Ab[rA * 32 + c0];
                a[mt][1] = Ab[(rA + 8) * 32 + c0];
                a[mt][2] = Ab[rA * 32 + c1];
                a[mt][3] = Ab[(rA + 8) * 32 + c1];
            }
#pragma unroll
            for (int nt = 0; nt < 2; nt++) {
                const int rB = wid * 16 + nt * 8 + ly;
                b[nt][0] = Bb[rB * 32 + c0];
                b[nt][1] = Bb[rB * 32 + c1];
            }
#pragma unroll
            for (int mt = 0; mt < 2; mt++)
#pragma unroll
                for (int nt = 0; nt < 2; nt++)
                    mma_tf32(c[mt][nt][0], c[mt][nt][1], c[mt][nt][2], c[mt][nt][3],
                             a[mt][0], a[mt][1], a[mt][2], a[mt][3],
                             b[nt][0], b[nt][1]);
        }
        __syncthreads();
    }

    // epilogue: bias + store
#pragma unroll
    for (int mt = 0; mt < 2; mt++) {
#pragma unroll
        for (int nt = 0; nt < 2; nt++) {
            const int col = e0 + wid * 16 + nt * 8 + 2 * lx;
            float bx0 = 0.f, bx1 = 0.f;
            if (bias) { bx0 = b0[col]; bx1 = b0[col + 1]; }
            const int rA = r0 + mt * 16 + ly;
            float2 v0 = make_float2(c[mt][nt][0] + bx0, c[mt][nt][1] + bx1);
            float2 v1 = make_float2(c[mt][nt][2] + bx0, c[mt][nt][3] + bx1);
            *(float2*)&C[(size_t)rA * DD + col]       = v0;
            *(float2*)&C[(size_t)(rA + 8) * DD + col] = v1;
        }
    }
}

// ---------------------------------------------------------------------------
// Score kernel: g_sc[n,l,m] = b1 + sum_d w1[d]*tanh(q[n,l,d]+mp[n,m,d])
// grid = 1024 blocks: n(4) x l-tile(32, 4 rows) x m-split(8, 32 m's).
// ---------------------------------------------------------------------------
__global__ __launch_bounds__(256, 2) void score_kernel(
    const float* __restrict__ w1, const float* __restrict__ b1)
{
    const int b = blockIdx.x;
    const int n = b >> 8;
    const int rem = b & 255;
    const int l0 = (rem >> 3) * 4;
    const int m0 = (rem & 7) * 32;
    const int t = threadIdx.x;
    const int w = t >> 5, lane = t & 31;

    float qr[4][16];
    float wr[16];
    {
        const float* qrow0 = g_q + (size_t)(n * LQ + l0) * DD;
#pragma unroll
        for (int l = 0; l < 4; l++) {
#pragma unroll
            for (int c = 0; c < 4; c++) {
                float4 v = *(const float4*)&qrow0[l * DD + c * 128 + lane * 4];
                qr[l][c * 4 + 0] = v.x; qr[l][c * 4 + 1] = v.y;
                qr[l][c * 4 + 2] = v.z; qr[l][c * 4 + 3] = v.w;
            }
        }
#pragma unroll
        for (int c = 0; c < 4; c++) {
            float4 v = *(const float4*)&w1[c * 128 + lane * 4];
            wr[c * 4 + 0] = v.x; wr[c * 4 + 1] = v.y;
            wr[c * 4 + 2] = v.z; wr[c * 4 + 3] = v.w;
        }
    }
    const float b1v = b1[0];

    const float* mpn = g_mp + (size_t)n * LM * DD;
#pragma unroll
    for (int mi = 0; mi < 4; mi++) {
        const int m = m0 + w * 4 + mi;
        const float* mrow = mpn + (size_t)m * DD;
        float mr[16];
#pragma unroll
        for (int c = 0; c < 4; c++) {
            float4 v = *(const float4*)&mrow[c * 128 + lane * 4];
            mr[c * 4 + 0] = v.x; mr[c * 4 + 1] = v.y;
            mr[c * 4 + 2] = v.z; mr[c * 4 + 3] = v.w;
        }
        float a[4] = {0.f, 0.f, 0.f, 0.f};
#pragma unroll
        for (int d = 0; d < 16; d++) {
            const float me = mr[d];
            const float wd = wr[d];
#pragma unroll
            for (int l = 0; l < 4; l++) {
                float x = qr[l][d] + me;
                float th;
                asm("tanh.approx.f32 %0, %1;" : "=f"(th) : "f"(x));
                a[l] = fmaf(wd, th, a[l]);
            }
        }
#pragma unroll
        for (int l = 0; l < 4; l++) {
#pragma unroll
            for (int o = 16; o > 0; o >>= 1)
                a[l] += __shfl_xor_sync(0xffffffffu, a[l], o);
        }
        if (lane < 4) {
            float v = (lane & 2) ? ((lane & 1) ? a[3] : a[2])
                                 : ((lane & 1) ? a[1] : a[0]);
            g_sc[(size_t)(n * LQ + l0 + lane) * LM + m] = v + b1v;
        }
    }
}

// ---------------------------------------------------------------------------
// Softmax + output: out[n,l,:] = softmax(mask(sc[n,l,:])) @ memory[n]
// grid = 512 blocks: n(4) x l-tile(32, 4 rows) x d-split(4, 128 d's).
// ---------------------------------------------------------------------------
__global__ __launch_bounds__(128) void out_kernel(
    const float* __restrict__ mem, const unsigned int* __restrict__ mask,
    float* __restrict__ out)
{
    __shared__ float att[4][LM];

    const int b = blockIdx.x;
    const int n = b >> 7;
    const int rem = b & 127;
    const int l0 = (rem >> 2) * 4;
    const int d0 = (rem & 3) * 128;
    const int t = threadIdx.x;
    const int w = t >> 5, lane = t & 31;

    {
        const int l = w;
        const float* srow = g_sc + (size_t)(n * LQ + l0 + l) * LM;
        const unsigned int* mrow = mask + (size_t)(n * LQ + l0 + l) * LM;
        const float NEG = -3.402823466e38f;
        float s[8];
        float mx = NEG;
#pragma unroll
        for (int k = 0; k < 8; k++) {
            int m = lane + 32 * k;
            float v = srow[m];
            if (mrow[m] == 0u) v = NEG;   // bool promoted: nonzero bits == true
            s[k] = v;
            mx = fmaxf(mx, v);
        }
#pragma unroll
        for (int o = 16; o > 0; o >>= 1)
            mx = fmaxf(mx, __shfl_xor_sync(0xffffffffu, mx, o));
        float sum = 0.f;
#pragma unroll
        for (int k = 0; k < 8; k++) {
            s[k] = __expf(s[k] - mx);
            sum += s[k];
        }
#pragma unroll
        for (int o = 16; o > 0; o >>= 1)
            sum += __shfl_xor_sync(0xffffffffu, sum, o);
        const float inv = 1.f / sum;
#pragma unroll
        for (int k = 0; k < 8; k++)
            att[l][lane + 32 * k] = s[k] * inv;
    }
    __syncthreads();

    {
        const int l = w;
        const int dbase = d0 + lane * 4;
        const float* memn = mem + (size_t)n * LM * DD + dbase;
        float4 o0 = make_float4(0.f, 0.f, 0.f, 0.f);
#pragma unroll 8
        for (int m = 0; m < LM; m++) {
            const float a = att[l][m];
            const float4 v = *(const float4*)&memn[(size_t)m * DD];
            o0.x = fmaf(a, v.x, o0.x); o0.y = fmaf(a, v.y, o0.y);
            o0.z = fmaf(a, v.z, o0.z); o0.w = fmaf(a, v.w, o0.w);
        }
        *(float4*)&out[(size_t)(n * LQ + l0 + l) * DD + dbase] = o0;
    }
}

extern "C" void kernel_launch(void* const* d_in, const int* in_sizes, int n_in,
                              void* d_out, int out_size)
{
    const float*        inp  = (const float*)d_in[0];        // (4,128,512)
    const float*        mem  = (const float*)d_in[1];        // (4,256,512)
    const unsigned int* mask = (const unsigned int*)d_in[2]; // (4,128,256) bool->4B
    const float*        W0   = (const float*)d_in[3];        // (512,1024)
    const float*        b0   = (const float*)d_in[4];        // (512)
    const float*        w1   = (const float*)d_in[5];        // (1,512)
    const float*        b1   = (const float*)d_in[6];        // (1)
    float* out = (float*)d_out;                              // (4,128,512)

    gemm_tc_kernel<<<384, 128>>>(inp, mem, W0, b0);
    score_kernel<<<1024, 256>>>(w1, b1);
    out_kernel<<<512, 128>>>(mem, mask, out);
}